// round 11
// baseline (speedup 1.0000x reference)
#include <cuda_runtime.h>
#include <mma.h>
#include <cuda_fp16.h>
#include <cstdint>

using namespace nvcuda;

#define B_  8
#define S_  2048
#define E_  2048
#define H_  16
#define D_  128
#define BH_ (B_ * H_)
#define NCHUNK_ 4
#define CHUNK_S_ (S_ / NCHUNK_)   // 512
#define EPS_ 1e-6f
#define DEN_SCALE_ 4096.0f
#define INV_DEN_SCALE_ (1.0f / 4096.0f)

// tf32 fragments (fused_kv phase 2 only)
typedef wmma::fragment<wmma::matrix_a, 16, 16, 8, wmma::precision::tf32, wmma::col_major> ATFrag;
typedef wmma::fragment<wmma::matrix_b, 16, 16, 8, wmma::precision::tf32, wmma::row_major> BFrag;
typedef wmma::fragment<wmma::accumulator, 16, 16, 8, float> CFrag;
// fp16 fragments
typedef wmma::fragment<wmma::matrix_a, 16, 16, 16, __half, wmma::row_major> AFragH;
typedef wmma::fragment<wmma::matrix_b, 16, 16, 16, __half, wmma::row_major> BFragH;
typedef wmma::fragment<wmma::accumulator, 16, 16, 16, float> CFragH;

__device__ __forceinline__ float phi_(float y) { return (y > 0.f) ? (y + 1.f) : expf(y); }
__device__ __forceinline__ float rtf32_(float y) { return wmma::__float_to_tf32(y); }

__device__ __forceinline__ void f4_to_h4(__half* smem, const float4 v) {
    __half2 h0 = __floats2half2_rn(v.x, v.y);
    __half2 h1 = __floats2half2_rn(v.z, v.w);
    uint2 u;
    u.x = *(uint32_t*)&h0;
    u.y = *(uint32_t*)&h1;
    *(uint2*)smem = u;
}

__device__ __forceinline__ void cpasync16(void* smem, const void* gmem) {
    uint32_t s = (uint32_t)__cvta_generic_to_shared(smem);
    asm volatile("cp.async.cg.shared.global [%0], [%1], 16;" :: "r"(s), "l"(gmem));
}
#define CP_COMMIT()  asm volatile("cp.async.commit_group;")
#define CP_WAIT(N)   asm volatile("cp.async.wait_group %0;" :: "n"(N))

// ---------------- scratch (__device__ globals; no allocation allowed) ----------------
__device__ float  g_kvp[(size_t)BH_ * NCHUNK_ * D_ * D_];   // 32 MB
__device__ float  g_ksp[(size_t)BH_ * NCHUNK_ * D_];
__device__ __half g_kvh[(size_t)BH_ * D_ * D_];             // 4 MB fp16 kv
__device__ float  g_ks [(size_t)BH_ * D_];
__device__ __half g_combh[(size_t)B_ * S_ * E_];            // 64 MB fp16 combined heads
__device__ __half g_woh [(size_t)E_ * E_];                  // 8 MB fp16 Wo

// ===========================================================================
// Prep: convert Wo -> fp16.
// ===========================================================================
__global__ void wo_half_kernel(const float4* __restrict__ src) {
    const int n4 = (E_ * E_) / 4;
    int i = blockIdx.x * blockDim.x + threadIdx.x;
    int stride = gridDim.x * blockDim.x;
    for (; i < n4; i += stride) {
        float4 v = src[i];
        __half2* d = (__half2*)&g_woh[(size_t)i * 4];
        d[0] = __floats2half2_rn(v.x, v.y);
        d[1] = __floats2half2_rn(v.z, v.w);
    }
}

// ===========================================================================
// Kernel A: fused K-proj, V-proj (fp16 mma), phi, partial kv (tf32) & ksum.
// (unchanged from passing round 10)
// ===========================================================================
union KvSmem {
    struct { __half XsH[32][40]; __half WkH[32][136]; __half WvH[32][136]; } p1;
    struct { float Kt[32][132]; float Vt[32][132]; } p2;
};

__global__ void __launch_bounds__(256) fused_kv_kernel(const float* __restrict__ x,
                                                       const float* __restrict__ Wk,
                                                       const float* __restrict__ Wv) {
    __shared__ KvSmem sm;

    const int chunk = blockIdx.x;
    const int bh    = blockIdx.y;
    const int b = bh / H_, h = bh % H_;

    const float* Wkh = Wk + (size_t)h * D_ * D_;
    const float* Wvh = Wv + (size_t)h * D_ * D_;
    const float* Xb  = x + (size_t)b * S_ * E_ + (size_t)h * D_;

    const int tid  = threadIdx.x;
    const int warp = tid >> 5;
    const int lane = tid & 31;
    const int wm1 = warp & 1;
    const int wn1 = warp >> 1;
    const int wm2 = warp & 3;
    const int wn2 = warp >> 2;

    CFrag acc_kv[2][4];
#pragma unroll
    for (int i = 0; i < 2; i++)
#pragma unroll
        for (int j = 0; j < 4; j++) wmma::fill_fragment(acc_kv[i][j], 0.f);

    float ksum_acc = 0.f;

    for (int sub = 0; sub < CHUNK_S_ / 32; sub++) {
        const int s0 = chunk * CHUNK_S_ + sub * 32;

        CFragH acck[2], accv[2];
#pragma unroll
        for (int j = 0; j < 2; j++) { wmma::fill_fragment(acck[j], 0.f); wmma::fill_fragment(accv[j], 0.f); }

        for (int k0 = 0; k0 < D_; k0 += 32) {
            {
                int r = tid >> 3, c4 = (tid & 7) * 4;
                f4_to_h4(&sm.p1.XsH[r][c4], *(const float4*)&Xb[(size_t)(s0 + r) * E_ + k0 + c4]);
            }
#pragma unroll
            for (int t = 0; t < 4; t++) {
                int f4i = tid + t * 256;
                int r = f4i >> 5, c4 = (f4i & 31) * 4;
                f4_to_h4(&sm.p1.WkH[r][c4], *(const float4*)&Wkh[(size_t)(k0 + r) * D_ + c4]);
                f4_to_h4(&sm.p1.WvH[r][c4], *(const float4*)&Wvh[(size_t)(k0 + r) * D_ + c4]);
            }
            __syncthreads();
#pragma unroll
            for (int kk = 0; kk < 2; kk++) {
                AFragH a;
                wmma::load_matrix_sync(a, &sm.p1.XsH[wm1 * 16][kk * 16], 40);
#pragma unroll
                for (int j = 0; j < 2; j++) {
                    BFragH bfr;
                    wmma::load_matrix_sync(bfr, &sm.p1.WkH[kk * 16][wn1 * 32 + j * 16], 136);
                    wmma::mma_sync(acck[j], a, bfr, acck[j]);
                    wmma::load_matrix_sync(bfr, &sm.p1.WvH[kk * 16][wn1 * 32 + j * 16], 136);
                    wmma::mma_sync(accv[j], a, bfr, accv[j]);
                }
            }
            __syncthreads();
        }
#pragma unroll
        for (int j = 0; j < 2; j++) {
#pragma unroll
            for (int e = 0; e < acck[j].num_elements; e++) acck[j].x[e] = rtf32_(phi_(acck[j].x[e]));
#pragma unroll
            for (int e = 0; e < accv[j].num_elements; e++) accv[j].x[e] = rtf32_(accv[j].x[e]);
            wmma::store_matrix_sync(&sm.p2.Kt[wm1 * 16][wn1 * 32 + j * 16], acck[j], 132, wmma::mem_row_major);
            wmma::store_matrix_sync(&sm.p2.Vt[wm1 * 16][wn1 * 32 + j * 16], accv[j], 132, wmma::mem_row_major);
        }
        __syncthreads();

        if (warp < 4) {
            const int col = warp * 32 + lane;
#pragma unroll 8
            for (int r = 0; r < 32; r++) ksum_acc += sm.p2.Kt[r][col];
        }

#pragma unroll
        for (int kk = 0; kk < 4; kk++) {
            ATFrag a2[2];
#pragma unroll
            for (int i = 0; i < 2; i++)
                wmma::load_matrix_sync(a2[i], &sm.p2.Kt[kk * 8][wm2 * 32 + i * 16], 132);
#pragma unroll
            for (int j = 0; j < 4; j++) {
                BFrag bfr;
                wmma::load_matrix_sync(bfr, &sm.p2.Vt[kk * 8][wn2 * 64 + j * 16], 132);
#pragma unroll
                for (int i = 0; i < 2; i++) wmma::mma_sync(acc_kv[i][j], a2[i], bfr, acc_kv[i][j]);
            }
        }
        __syncthreads();
    }

    float* kvp = g_kvp + ((size_t)bh * NCHUNK_ + chunk) * D_ * D_;
#pragma unroll
    for (int i = 0; i < 2; i++)
#pragma unroll
        for (int j = 0; j < 4; j++)
            wmma::store_matrix_sync(&kvp[(size_t)(wm2 * 32 + i * 16) * D_ + wn2 * 64 + j * 16],
                                    acc_kv[i][j], D_, wmma::mem_row_major);
    if (warp < 4)
        g_ksp[((size_t)bh * NCHUNK_ + chunk) * D_ + warp * 32 + lane] = ksum_acc;
}

// ===========================================================================
// Kernel A2: reduce the NCHUNK partials; kv -> fp16. (unchanged)
// ===========================================================================
__global__ void reduce_kernel() {
    const int bh = blockIdx.x;
    const int tid = threadIdx.x;
    const float* kvp = g_kvp + (size_t)bh * NCHUNK_ * D_ * D_;
    __half* kv = g_kvh + (size_t)bh * D_ * D_;
    for (int i = tid; i < D_ * D_; i += 256) {
        float s = 0.f;
#pragma unroll
        for (int c = 0; c < NCHUNK_; c++) s += kvp[(size_t)c * D_ * D_ + i];
        kv[i] = __float2half_rn(s);
    }
    if (tid < D_) {
        const float* ksp = g_ksp + (size_t)bh * NCHUNK_ * D_;
        float s = 0.f;
#pragma unroll
        for (int c = 0; c < NCHUNK_; c++) s += ksp[(size_t)c * D_ + tid];
        g_ks[(size_t)bh * D_ + tid] = s;
    }
}

// ===========================================================================
// Kernel B: fused Q-proj + phi + ctx, all-fp16 mma. (unchanged from round 10)
// ===========================================================================
union CtxU {
    struct { __half XsH[32][40]; __half WH[32][136]; } p1;
    struct { __half QtH[32][136]; __half kvH[32][136]; } p2;
};

__global__ void __launch_bounds__(256) fused_ctx_kernel(const float* __restrict__ x,
                                                        const float* __restrict__ Wq) {
    __shared__ float QtF[32][132];
    __shared__ CtxU u;
    __shared__ float ksum_s[128];
    __shared__ float den_s[32];

    const int stile = blockIdx.x;
    const int bh    = blockIdx.y;
    const int b = bh / H_, h = bh % H_;

    const float* Wqh = Wq + (size_t)h * D_ * D_;
    const float* Xb  = x + (size_t)b * S_ * E_ + (size_t)h * D_;
    const __half* kv = g_kvh + (size_t)bh * D_ * D_;

    const int tid  = threadIdx.x;
    const int warp = tid >> 5;
    const int wm = warp & 1;
    const int wn = warp >> 1;
    const int s0 = stile * 32;

    if (tid < 128) ksum_s[tid] = g_ks[(size_t)bh * D_ + tid];

    CFragH acc[2];
#pragma unroll
    for (int j = 0; j < 2; j++) wmma::fill_fragment(acc[j], 0.f);

    for (int k0 = 0; k0 < D_; k0 += 32) {
        {
            int r = tid >> 3, c4 = (tid & 7) * 4;
            f4_to_h4(&u.p1.XsH[r][c4], *(const float4*)&Xb[(size_t)(s0 + r) * E_ + k0 + c4]);
        }
#pragma unroll
        for (int t = 0; t < 4; t++) {
            int f4i = tid + t * 256;
            int r = f4i >> 5, c4 = (f4i & 31) * 4;
            f4_to_h4(&u.p1.WH[r][c4], *(const float4*)&Wqh[(size_t)(k0 + r) * D_ + c4]);
        }
        __syncthreads();
#pragma unroll
        for (int kk = 0; kk < 2; kk++) {
            AFragH a;
            wmma::load_matrix_sync(a, &u.p1.XsH[wm * 16][kk * 16], 40);
#pragma unroll
            for (int j = 0; j < 2; j++) {
                BFragH bfr;
                wmma::load_matrix_sync(bfr, &u.p1.WH[kk * 16][wn * 32 + j * 16], 136);
                wmma::mma_sync(acc[j], a, bfr, acc[j]);
            }
        }
        __syncthreads();
    }
#pragma unroll
    for (int j = 0; j < 2; j++) {
#pragma unroll
        for (int e = 0; e < acc[j].num_elements; e++) acc[j].x[e] = phi_(acc[j].x[e]);
        wmma::store_matrix_sync(&QtF[wm * 16][wn * 32 + j * 16], acc[j], 132, wmma::mem_row_major);
    }
    __syncthreads();

    if (tid < 32) {
        float dsum = 0.f;
#pragma unroll
        for (int c = 0; c < 128; c++) dsum = fmaf(QtF[tid][c], ksum_s[c], dsum);
        den_s[tid] = DEN_SCALE_ / (dsum + EPS_);
    }
    __syncthreads();
#pragma unroll
    for (int t = 0; t < 8; t++) {
        int i = tid + t * 256;
        int r = i >> 6, c2 = i & 63;
        float sc = den_s[r];
        *(__half2*)&u.p2.QtH[r][c2 * 2] =
            __floats2half2_rn(QtF[r][c2 * 2] * sc, QtF[r][c2 * 2 + 1] * sc);
    }
    __syncthreads();

#pragma unroll
    for (int j = 0; j < 2; j++) wmma::fill_fragment(acc[j], 0.f);

    for (int k0 = 0; k0 < D_; k0 += 32) {
#pragma unroll
        for (int t = 0; t < 4; t++) {
            int f = tid + t * 256;
            int r = f >> 5, c4 = (f & 31) * 4;
            *(uint2*)&u.p2.kvH[r][c4] = *(const uint2*)&kv[(size_t)(k0 + r) * D_ + c4];
        }
        __syncthreads();
#pragma unroll
        for (int kk = 0; kk < 2; kk++) {
            AFragH a;
            wmma::load_matrix_sync(a, &u.p2.QtH[wm * 16][k0 + kk * 16], 136);
#pragma unroll
            for (int j = 0; j < 2; j++) {
                BFragH bfr;
                wmma::load_matrix_sync(bfr, &u.p2.kvH[kk * 16][wn * 32 + j * 16], 136);
                wmma::mma_sync(acc[j], a, bfr, acc[j]);
            }
        }
        __syncthreads();
    }

#pragma unroll
    for (int j = 0; j < 2; j++)
        wmma::store_matrix_sync(&QtF[wm * 16][wn * 32 + j * 16], acc[j], 132, wmma::mem_row_major);
    __syncthreads();
#pragma unroll
    for (int t = 0; t < 8; t++) {
        int i = tid + t * 256;
        int r = i >> 6, c2 = i & 63;
        __half2 v = __floats2half2_rn(QtF[r][c2 * 2] * INV_DEN_SCALE_,
                                      QtF[r][c2 * 2 + 1] * INV_DEN_SCALE_);
        *(__half2*)&g_combh[((size_t)(b * S_ + s0 + r)) * E_ + h * D_ + c2 * 2] = v;
    }
}

// ===========================================================================
// Kernel C v3: out = g_combh @ g_woh + bo (fp16 wmma), 256x128 tile,
// 512 threads (16 warps, 64x32 warp tiles), 3-stage cp.async pipeline,
// ONE __syncthreads per k-iteration.  Dynamic smem: 96,000 B.
// ===========================================================================
#define OC_BM 256
#define OC_BN 128
#define OC_BK 32
#define OC_NIT (E_ / OC_BK)   // 64

struct OutSmem {
    __half Ah[3][OC_BM][40];     // 61,440 B
    __half Bh[3][OC_BK][136];    // 26,112 B
    float  BiasS[16][132];       //  8,448 B
};
#define OUT_SMEM_BYTES ((int)sizeof(OutSmem))

__global__ void __launch_bounds__(512, 1) out_kernel(const float* __restrict__ bo,
                                                     float* __restrict__ out) {
    extern __shared__ __align__(16) char out_smem_raw[];
    OutSmem& sm = *reinterpret_cast<OutSmem*>(out_smem_raw);

    const int col0 = blockIdx.x * OC_BN;
    const int row0 = blockIdx.y * OC_BM;
    const int tid  = threadIdx.x;
    const int warp = tid >> 5;
    const int wm = warp & 3;    // rows wm*64
    const int wn = warp >> 2;   // cols wn*32

    // A tile 256x32 half = 1024 x 16B chunks (4/row), 2 per thread
    const int ar0 = tid >> 2,         ac0 = (tid & 3) * 8;
    const int ar1 = (tid + 512) >> 2, ac1 = ac0;
    // B tile 32x128 half = 512 chunks (16/row), 1 per thread
    const int br0 = tid >> 4,         bc0 = (tid & 15) * 8;

    const __half* Ag = g_combh + (size_t)row0 * E_;
    const __half* Bg = g_woh + (size_t)col0;

    // replicated bias tile -> init accumulators with bias
#pragma unroll
    for (int t = 0; t < 4; t++) {
        int i = tid + t * 512;
        int r = i >> 7, c = i & 127;
        sm.BiasS[r][c] = bo[col0 + c];
    }
    __syncthreads();

    CFragH acc[4][2];
#pragma unroll
    for (int i = 0; i < 4; i++)
#pragma unroll
        for (int j = 0; j < 2; j++)
            wmma::load_matrix_sync(acc[i][j], &sm.BiasS[0][wn * 32 + j * 16], 132, wmma::mem_row_major);
    __syncthreads();

    // ---- prologue: stages 0 and 1 ----
#pragma unroll
    for (int s = 0; s < 2; s++) {
        const int k0 = s * OC_BK;
        cpasync16(&sm.Ah[s][ar0][ac0], &Ag[(size_t)ar0 * E_ + k0 + ac0]);
        cpasync16(&sm.Ah[s][ar1][ac1], &Ag[(size_t)ar1 * E_ + k0 + ac1]);
        cpasync16(&sm.Bh[s][br0][bc0], &Bg[(size_t)(k0 + br0) * E_ + bc0]);
        CP_COMMIT();
    }

    for (int it = 0; it < OC_NIT; it++) {
        const int cur = it % 3;
        CP_WAIT(1);              // stage `cur` complete (stage it+1 may fly)
        __syncthreads();         // all warps done reading stage (it+2)%3 from iter it-1

        if (it + 2 < OC_NIT) {
            const int nxt = (it + 2) % 3;
            const int k0 = (it + 2) * OC_BK;
            cpasync16(&sm.Ah[nxt][ar0][ac0], &Ag[(size_t)ar0 * E_ + k0 + ac0]);
            cpasync16(&sm.Ah[nxt][ar1][ac1], &Ag[(size_t)ar1 * E_ + k0 + ac1]);
            cpasync16(&sm.Bh[nxt][br0][bc0], &Bg[(size_t)(k0 + br0) * E_ + bc0]);
        }
        CP_COMMIT();             // empty group in tail keeps WAIT(1) depth honest

#pragma unroll
        for (int kk = 0; kk < OC_BK / 16; kk++) {
            AFragH a[4];
#pragma unroll
            for (int i = 0; i < 4; i++)
                wmma::load_matrix_sync(a[i], &sm.Ah[cur][wm * 64 + i * 16][kk * 16], 40);
#pragma unroll
            for (int j = 0; j < 2; j++) {
                BFragH bfr;
                wmma::load_matrix_sync(bfr, &sm.Bh[cur][kk * 16][wn * 32 + j * 16], 136);
#pragma unroll
                for (int i = 0; i < 4; i++) wmma::mma_sync(acc[i][j], a[i], bfr, acc[i][j]);
            }
        }
    }

#pragma unroll
    for (int i = 0; i < 4; i++)
#pragma unroll
        for (int j = 0; j < 2; j++)
            wmma::store_matrix_sync(out + (size_t)(row0 + wm * 64 + i * 16) * E_ + col0 + wn * 32 + j * 16,
                                    acc[i][j], E_, wmma::mem_row_major);
}

// ===========================================================================
extern "C" void kernel_launch(void* const* d_in, const int* in_sizes, int n_in,
                              void* d_out, int out_size) {
    const float* x  = (const float*)d_in[0];
    const float* Wq = (const float*)d_in[1];
    const float* Wk = (const float*)d_in[2];
    const float* Wv = (const float*)d_in[3];
    const float* Wo = (const float*)d_in[4];
    const float* bo = (const float*)d_in[5];
    float* out = (float*)d_out;

    (void)cudaFuncSetAttribute(out_kernel, cudaFuncAttributeMaxDynamicSharedMemorySize, OUT_SMEM_BYTES);

    wo_half_kernel<<<1024, 256>>>((const float4*)Wo);
    fused_kv_kernel<<<dim3(NCHUNK_, BH_), 256>>>(x, Wk, Wv);
    reduce_kernel<<<BH_, 256>>>();
    fused_ctx_kernel<<<dim3(S_ / 32, BH_), 256>>>(x, Wq);
    out_kernel<<<dim3(E_ / OC_BN, (B_ * S_) / OC_BM), 512, OUT_SMEM_BYTES>>>(bo, out);
}

// round 13
// speedup vs baseline: 1.1782x; 1.1782x over previous
#include <cuda_runtime.h>
#include <mma.h>
#include <cuda_fp16.h>
#include <cstdint>

using namespace nvcuda;

#define B_  8
#define S_  2048
#define E_  2048
#define H_  16
#define D_  128
#define BH_ (B_ * H_)
#define NCHUNK_ 4
#define CHUNK_S_ (S_ / NCHUNK_)   // 512
#define EPS_ 1e-6f
#define DEN_SCALE_ 4096.0f
#define INV_DEN_SCALE_ (1.0f / 4096.0f)

// fp16 fragments
typedef wmma::fragment<wmma::matrix_a, 16, 16, 16, __half, wmma::row_major> AFragH;
typedef wmma::fragment<wmma::matrix_a, 16, 16, 16, __half, wmma::col_major> ATFragH;
typedef wmma::fragment<wmma::matrix_b, 16, 16, 16, __half, wmma::row_major> BFragH;
typedef wmma::fragment<wmma::accumulator, 16, 16, 16, float> CFragH;

__device__ __forceinline__ float phi_(float y) { return (y > 0.f) ? (y + 1.f) : expf(y); }

__device__ __forceinline__ void f4_to_h4(__half* smem, const float4 v) {
    __half2 h0 = __floats2half2_rn(v.x, v.y);
    __half2 h1 = __floats2half2_rn(v.z, v.w);
    uint2 u;
    u.x = *(uint32_t*)&h0;
    u.y = *(uint32_t*)&h1;
    *(uint2*)smem = u;
}

__device__ __forceinline__ void cpasync16(void* smem, const void* gmem) {
    uint32_t s = (uint32_t)__cvta_generic_to_shared(smem);
    asm volatile("cp.async.cg.shared.global [%0], [%1], 16;" :: "r"(s), "l"(gmem));
}
#define CP_COMMIT()  asm volatile("cp.async.commit_group;")
#define CP_WAIT(N)   asm volatile("cp.async.wait_group %0;" :: "n"(N))

// ---------------- scratch (__device__ globals; no allocation allowed) ----------------
__device__ float  g_kvp[(size_t)BH_ * NCHUNK_ * D_ * D_];   // 32 MB
__device__ float  g_ksp[(size_t)BH_ * NCHUNK_ * D_];
__device__ __half g_kvh[(size_t)BH_ * D_ * D_];             // 4 MB fp16 kv
__device__ float  g_ks [(size_t)BH_ * D_];
__device__ __half g_combh[(size_t)B_ * S_ * E_];            // 64 MB fp16 combined heads
__device__ __half g_woh [(size_t)E_ * E_];                  // 8 MB fp16 Wo

// ===========================================================================
// Prep: convert Wo -> fp16.
// ===========================================================================
__global__ void wo_half_kernel(const float4* __restrict__ src) {
    const int n4 = (E_ * E_) / 4;
    int i = blockIdx.x * blockDim.x + threadIdx.x;
    int stride = gridDim.x * blockDim.x;
    for (; i < n4; i += stride) {
        float4 v = src[i];
        __half2* d = (__half2*)&g_woh[(size_t)i * 4];
        d[0] = __floats2half2_rn(v.x, v.y);
        d[1] = __floats2half2_rn(v.z, v.w);
    }
}

// ===========================================================================
// Kernel A v2: fused K-proj, V-proj, phi, partial kv & ksum — ALL fp16 mma.
// grid = (NCHUNK, BH), block 256 (8 warps). 32-row sub-tiles. Phase-2
// fp16 (col-major A = free transpose); float->half via one staged tile.
// ===========================================================================
union KvSmem {
    struct { __half XsH[32][40]; __half WkH[32][136]; __half WvH[32][136]; } p1;    // 19,968 B
    struct { float StageF[32][132]; __half KtH[32][136]; __half VtH[32][136]; } p2; // 34,304 B
};

__global__ void __launch_bounds__(256) fused_kv_kernel(const float* __restrict__ x,
                                                       const float* __restrict__ Wk,
                                                       const float* __restrict__ Wv) {
    __shared__ KvSmem sm;

    const int chunk = blockIdx.x;
    const int bh    = blockIdx.y;
    const int b = bh / H_, h = bh % H_;

    const float* Wkh = Wk + (size_t)h * D_ * D_;
    const float* Wvh = Wv + (size_t)h * D_ * D_;
    const float* Xb  = x + (size_t)b * S_ * E_ + (size_t)h * D_;

    const int tid  = threadIdx.x;
    const int warp = tid >> 5;
    const int lane = tid & 31;
    const int wm1 = warp & 1;    // phase1: 16-row blocks
    const int wn1 = warp >> 1;   // phase1: 32-col blocks
    const int wm2 = warp & 3;    // phase2: 32-row blocks
    const int wn2 = warp >> 2;   // phase2: 64-col blocks

    CFragH acc_kv[2][4];
#pragma unroll
    for (int i = 0; i < 2; i++)
#pragma unroll
        for (int j = 0; j < 4; j++) wmma::fill_fragment(acc_kv[i][j], 0.f);

    float ksum_acc = 0.f;

    for (int sub = 0; sub < CHUNK_S_ / 32; sub++) {
        const int s0 = chunk * CHUNK_S_ + sub * 32;

        // ---- phase 1 (fp16): K/V projections for 32 rows ----
        CFragH acck[2], accv[2];
#pragma unroll
        for (int j = 0; j < 2; j++) { wmma::fill_fragment(acck[j], 0.f); wmma::fill_fragment(accv[j], 0.f); }

        for (int k0 = 0; k0 < D_; k0 += 32) {
            {
                int r = tid >> 3, c4 = (tid & 7) * 4;
                f4_to_h4(&sm.p1.XsH[r][c4], *(const float4*)&Xb[(size_t)(s0 + r) * E_ + k0 + c4]);
            }
#pragma unroll
            for (int t = 0; t < 4; t++) {
                int f4i = tid + t * 256;
                int r = f4i >> 5, c4 = (f4i & 31) * 4;
                f4_to_h4(&sm.p1.WkH[r][c4], *(const float4*)&Wkh[(size_t)(k0 + r) * D_ + c4]);
                f4_to_h4(&sm.p1.WvH[r][c4], *(const float4*)&Wvh[(size_t)(k0 + r) * D_ + c4]);
            }
            __syncthreads();
#pragma unroll
            for (int kk = 0; kk < 2; kk++) {
                AFragH a;
                wmma::load_matrix_sync(a, &sm.p1.XsH[wm1 * 16][kk * 16], 40);
#pragma unroll
                for (int j = 0; j < 2; j++) {
                    BFragH bfr;
                    wmma::load_matrix_sync(bfr, &sm.p1.WkH[kk * 16][wn1 * 32 + j * 16], 136);
                    wmma::mma_sync(acck[j], a, bfr, acck[j]);
                    wmma::load_matrix_sync(bfr, &sm.p1.WvH[kk * 16][wn1 * 32 + j * 16], 136);
                    wmma::mma_sync(accv[j], a, bfr, accv[j]);
                }
            }
            __syncthreads();
        }

        // ---- stage K: phi(acck) -> StageF (float), ksum, convert -> KtH ----
#pragma unroll
        for (int j = 0; j < 2; j++) {
#pragma unroll
            for (int e = 0; e < acck[j].num_elements; e++) acck[j].x[e] = phi_(acck[j].x[e]);
            wmma::store_matrix_sync(&sm.p2.StageF[wm1 * 16][wn1 * 32 + j * 16], acck[j], 132, wmma::mem_row_major);
        }
        __syncthreads();
        if (warp < 4) {
            const int col = warp * 32 + lane;
#pragma unroll 8
            for (int r = 0; r < 32; r++) ksum_acc += sm.p2.StageF[r][col];
        }
#pragma unroll
        for (int t = 0; t < 8; t++) {
            int i = tid + t * 256;           // 32 rows x 64 half2
            int r = i >> 6, c2 = i & 63;
            *(__half2*)&sm.p2.KtH[r][c2 * 2] =
                __floats2half2_rn(sm.p2.StageF[r][c2 * 2], sm.p2.StageF[r][c2 * 2 + 1]);
        }
        __syncthreads();

        // ---- stage V: accv -> StageF -> VtH ----
#pragma unroll
        for (int j = 0; j < 2; j++)
            wmma::store_matrix_sync(&sm.p2.StageF[wm1 * 16][wn1 * 32 + j * 16], accv[j], 132, wmma::mem_row_major);
        __syncthreads();
#pragma unroll
        for (int t = 0; t < 8; t++) {
            int i = tid + t * 256;
            int r = i >> 6, c2 = i & 63;
            *(__half2*)&sm.p2.VtH[r][c2 * 2] =
                __floats2half2_rn(sm.p2.StageF[r][c2 * 2], sm.p2.StageF[r][c2 * 2 + 1]);
        }
        __syncthreads();

        // ---- phase 2 (fp16): kv += KtH^T @ VtH ----
#pragma unroll
        for (int kk = 0; kk < 2; kk++) {
            ATFragH a2[2];
#pragma unroll
            for (int i = 0; i < 2; i++)
                wmma::load_matrix_sync(a2[i], &sm.p2.KtH[kk * 16][wm2 * 32 + i * 16], 136);
#pragma unroll
            for (int j = 0; j < 4; j++) {
                BFragH bfr;
                wmma::load_matrix_sync(bfr, &sm.p2.VtH[kk * 16][wn2 * 64 + j * 16], 136);
#pragma unroll
                for (int i = 0; i < 2; i++) wmma::mma_sync(acc_kv[i][j], a2[i], bfr, acc_kv[i][j]);
            }
        }
        __syncthreads();   // KtH/VtH overlap p1; protect before next sub-tile
    }

    float* kvp = g_kvp + ((size_t)bh * NCHUNK_ + chunk) * D_ * D_;
#pragma unroll
    for (int i = 0; i < 2; i++)
#pragma unroll
        for (int j = 0; j < 4; j++)
            wmma::store_matrix_sync(&kvp[(size_t)(wm2 * 32 + i * 16) * D_ + wn2 * 64 + j * 16],
                                    acc_kv[i][j], D_, wmma::mem_row_major);
    if (warp < 4)
        g_ksp[((size_t)bh * NCHUNK_ + chunk) * D_ + warp * 32 + lane] = ksum_acc;
}

// ===========================================================================
// Kernel A2: reduce the NCHUNK partials; kv -> fp16. (unchanged)
// ===========================================================================
__global__ void reduce_kernel() {
    const int bh = blockIdx.x;
    const int tid = threadIdx.x;
    const float* kvp = g_kvp + (size_t)bh * NCHUNK_ * D_ * D_;
    __half* kv = g_kvh + (size_t)bh * D_ * D_;
    for (int i = tid; i < D_ * D_; i += 256) {
        float s = 0.f;
#pragma unroll
        for (int c = 0; c < NCHUNK_; c++) s += kvp[(size_t)c * D_ * D_ + i];
        kv[i] = __float2half_rn(s);
    }
    if (tid < D_) {
        const float* ksp = g_ksp + (size_t)bh * NCHUNK_ * D_;
        float s = 0.f;
#pragma unroll
        for (int c = 0; c < NCHUNK_; c++) s += ksp[(size_t)c * D_ + tid];
        g_ks[(size_t)bh * D_ + tid] = s;
    }
}

// ===========================================================================
// Kernel B: fused Q-proj + phi + ctx, all-fp16 mma. (unchanged from round 10)
// ===========================================================================
union CtxU {
    struct { __half XsH[32][40]; __half WH[32][136]; } p1;
    struct { __half QtH[32][136]; __half kvH[32][136]; } p2;
};

__global__ void __launch_bounds__(256) fused_ctx_kernel(const float* __restrict__ x,
                                                        const float* __restrict__ Wq) {
    __shared__ float QtF[32][132];
    __shared__ CtxU u;
    __shared__ float ksum_s[128];
    __shared__ float den_s[32];

    const int stile = blockIdx.x;
    const int bh    = blockIdx.y;
    const int b = bh / H_, h = bh % H_;

    const float* Wqh = Wq + (size_t)h * D_ * D_;
    const float* Xb  = x + (size_t)b * S_ * E_ + (size_t)h * D_;
    const __half* kv = g_kvh + (size_t)bh * D_ * D_;

    const int tid  = threadIdx.x;
    const int warp = tid >> 5;
    const int wm = warp & 1;
    const int wn = warp >> 1;
    const int s0 = stile * 32;

    if (tid < 128) ksum_s[tid] = g_ks[(size_t)bh * D_ + tid];

    CFragH acc[2];
#pragma unroll
    for (int j = 0; j < 2; j++) wmma::fill_fragment(acc[j], 0.f);

    for (int k0 = 0; k0 < D_; k0 += 32) {
        {
            int r = tid >> 3, c4 = (tid & 7) * 4;
            f4_to_h4(&u.p1.XsH[r][c4], *(const float4*)&Xb[(size_t)(s0 + r) * E_ + k0 + c4]);
        }
#pragma unroll
        for (int t = 0; t < 4; t++) {
            int f4i = tid + t * 256;
            int r = f4i >> 5, c4 = (f4i & 31) * 4;
            f4_to_h4(&u.p1.WH[r][c4], *(const float4*)&Wqh[(size_t)(k0 + r) * D_ + c4]);
        }
        __syncthreads();
#pragma unroll
        for (int kk = 0; kk < 2; kk++) {
            AFragH a;
            wmma::load_matrix_sync(a, &u.p1.XsH[wm * 16][kk * 16], 40);
#pragma unroll
            for (int j = 0; j < 2; j++) {
                BFragH bfr;
                wmma::load_matrix_sync(bfr, &u.p1.WH[kk * 16][wn * 32 + j * 16], 136);
                wmma::mma_sync(acc[j], a, bfr, acc[j]);
            }
        }
        __syncthreads();
    }
#pragma unroll
    for (int j = 0; j < 2; j++) {
#pragma unroll
        for (int e = 0; e < acc[j].num_elements; e++) acc[j].x[e] = phi_(acc[j].x[e]);
        wmma::store_matrix_sync(&QtF[wm * 16][wn * 32 + j * 16], acc[j], 132, wmma::mem_row_major);
    }
    __syncthreads();

    if (tid < 32) {
        float dsum = 0.f;
#pragma unroll
        for (int c = 0; c < 128; c++) dsum = fmaf(QtF[tid][c], ksum_s[c], dsum);
        den_s[tid] = DEN_SCALE_ / (dsum + EPS_);
    }
    __syncthreads();
#pragma unroll
    for (int t = 0; t < 8; t++) {
        int i = tid + t * 256;
        int r = i >> 6, c2 = i & 63;
        float sc = den_s[r];
        *(__half2*)&u.p2.QtH[r][c2 * 2] =
            __floats2half2_rn(QtF[r][c2 * 2] * sc, QtF[r][c2 * 2 + 1] * sc);
    }
    __syncthreads();

#pragma unroll
    for (int j = 0; j < 2; j++) wmma::fill_fragment(acc[j], 0.f);

    for (int k0 = 0; k0 < D_; k0 += 32) {
#pragma unroll
        for (int t = 0; t < 4; t++) {
            int f = tid + t * 256;
            int r = f >> 5, c4 = (f & 31) * 4;
            *(uint2*)&u.p2.kvH[r][c4] = *(const uint2*)&kv[(size_t)(k0 + r) * D_ + c4];
        }
        __syncthreads();
#pragma unroll
        for (int kk = 0; kk < 2; kk++) {
            AFragH a;
            wmma::load_matrix_sync(a, &u.p2.QtH[wm * 16][k0 + kk * 16], 136);
#pragma unroll
            for (int j = 0; j < 2; j++) {
                BFragH bfr;
                wmma::load_matrix_sync(bfr, &u.p2.kvH[kk * 16][wn * 32 + j * 16], 136);
                wmma::mma_sync(acc[j], a, bfr, acc[j]);
            }
        }
        __syncthreads();
    }

#pragma unroll
    for (int j = 0; j < 2; j++)
        wmma::store_matrix_sync(&QtF[wm * 16][wn * 32 + j * 16], acc[j], 132, wmma::mem_row_major);
    __syncthreads();
#pragma unroll
    for (int t = 0; t < 8; t++) {
        int i = tid + t * 256;
        int r = i >> 6, c2 = i & 63;
        __half2 v = __floats2half2_rn(QtF[r][c2 * 2] * INV_DEN_SCALE_,
                                      QtF[r][c2 * 2 + 1] * INV_DEN_SCALE_);
        *(__half2*)&g_combh[((size_t)(b * S_ + s0 + r)) * E_ + h * D_ + c2 * 2] = v;
    }
}

// ===========================================================================
// Kernel C: out = g_combh @ g_woh + bo (fp16 wmma m16n16k16, fp32 accum).
// Round-10 passing version (2-stage, 128x128, 2 CTA/SM).
// ===========================================================================
#define OKH_TK 32
#define OKH_NIT (E_ / OKH_TK)   // 64

__global__ void __launch_bounds__(256, 2) out_kernel(const float* __restrict__ bo,
                                                     float* __restrict__ out) {
    __shared__ __align__(16) __half Ah[2][128][40];
    __shared__ __align__(16) __half Bh[2][OKH_TK][136];
    __shared__ __align__(16) float BiasS[16][132];

    const int col0 = blockIdx.x * 128;
    const int row0 = blockIdx.y * 128;
    const int tid  = threadIdx.x;
    const int warp = tid >> 5;
    const int wm = warp & 3;
    const int wn = warp >> 2;

    const int ar0 = tid >> 2,         ac0 = (tid & 3) * 8;
    const int ar1 = (tid + 256) >> 2, ac1 = ac0;
    const int br0 = tid >> 4,         bc0 = (tid & 15) * 8;
    const int br1 = (tid + 256) >> 4, bc1 = bc0;

    const __half* Ag = g_combh + (size_t)row0 * E_;
    const __half* Bg = g_woh + (size_t)col0;

#pragma unroll
    for (int t = 0; t < 8; t++) {
        int i = tid + t * 256;
        int r = i >> 7, c = i & 127;
        BiasS[r][c] = bo[col0 + c];
    }
    __syncthreads();

    CFragH acc[2][4];
#pragma unroll
    for (int i = 0; i < 2; i++)
#pragma unroll
        for (int j = 0; j < 4; j++)
            wmma::load_matrix_sync(acc[i][j], &BiasS[0][wn * 64 + j * 16], 132, wmma::mem_row_major);
    __syncthreads();

    {
        cpasync16(&Ah[0][ar0][ac0], &Ag[(size_t)ar0 * E_ + ac0]);
        cpasync16(&Ah[0][ar1][ac1], &Ag[(size_t)ar1 * E_ + ac1]);
        cpasync16(&Bh[0][br0][bc0], &Bg[(size_t)br0 * E_ + bc0]);
        cpasync16(&Bh[0][br1][bc1], &Bg[(size_t)br1 * E_ + bc1]);
    }
    CP_COMMIT();

    for (int it = 0; it < OKH_NIT; it++) {
        const int cur = it & 1;
        if (it + 1 < OKH_NIT) {
            const int nxt = cur ^ 1;
            const int k0 = (it + 1) * OKH_TK;
            cpasync16(&Ah[nxt][ar0][ac0], &Ag[(size_t)ar0 * E_ + k0 + ac0]);
            cpasync16(&Ah[nxt][ar1][ac1], &Ag[(size_t)ar1 * E_ + k0 + ac1]);
            cpasync16(&Bh[nxt][br0][bc0], &Bg[(size_t)(k0 + br0) * E_ + bc0]);
            cpasync16(&Bh[nxt][br1][bc1], &Bg[(size_t)(k0 + br1) * E_ + bc1]);
        }
        CP_COMMIT();
        CP_WAIT(1);
        __syncthreads();

#pragma unroll
        for (int kk = 0; kk < OKH_TK / 16; kk++) {
            AFragH a[2];
#pragma unroll
            for (int i = 0; i < 2; i++)
                wmma::load_matrix_sync(a[i], &Ah[cur][wm * 32 + i * 16][kk * 16], 40);
#pragma unroll
            for (int j = 0; j < 4; j++) {
                BFragH bfr;
                wmma::load_matrix_sync(bfr, &Bh[cur][kk * 16][wn * 64 + j * 16], 136);
#pragma unroll
                for (int i = 0; i < 2; i++) wmma::mma_sync(acc[i][j], a[i], bfr, acc[i][j]);
            }
        }
        __syncthreads();
    }

#pragma unroll
    for (int i = 0; i < 2; i++)
#pragma unroll
        for (int j = 0; j < 4; j++)
            wmma::store_matrix_sync(out + (size_t)(row0 + wm * 32 + i * 16) * E_ + col0 + wn * 64 + j * 16,
                                    acc[i][j], E_, wmma::mem_row_major);
}

// ===========================================================================
extern "C" void kernel_launch(void* const* d_in, const int* in_sizes, int n_in,
                              void* d_out, int out_size) {
    const float* x  = (const float*)d_in[0];
    const float* Wq = (const float*)d_in[1];
    const float* Wk = (const float*)d_in[2];
    const float* Wv = (const float*)d_in[3];
    const float* Wo = (const float*)d_in[4];
    const float* bo = (const float*)d_in[5];
    float* out = (float*)d_out;

    wo_half_kernel<<<1024, 256>>>((const float4*)Wo);
    fused_kv_kernel<<<dim3(NCHUNK_, BH_), 256>>>(x, Wk, Wv);
    reduce_kernel<<<BH_, 256>>>();
    fused_ctx_kernel<<<dim3(S_ / 32, BH_), 256>>>(x, Wq);
    out_kernel<<<dim3(E_ / 128, (B_ * S_) / 128), 256>>>(bo, out);
}